// round 3
// baseline (speedup 1.0000x reference)
#include <cuda_runtime.h>
#include <math.h>

// Problem constants (fixed instance)
#define B_   2
#define L_   8192
#define G_   256
#define DG_  8
#define D_   2048          // G_*DG_
#define M_   8192          // complex FFT length (= L)
#define NF_  16384         // real FFT length (2L)
#define HFS_ 8208          // Hf row stride (>= 8193, 16B-multiple)

// -------- device scratch (static: no runtime allocation allowed) ----------
__device__ float  g_kvt[(size_t)B_ * D_ * L_];   // (B, D, L) kv, then y in place
__device__ float2 g_Hf[(size_t)G_ * HFS_];       // rfft(h_g) bins 0..8192
__device__ float2 g_tw[M_];                      // e^{-2*pi*i*k/16384}, k<8192

// -------- complex helpers --------------------------------------------------
__device__ __forceinline__ float2 cadd(float2 a, float2 b){ return make_float2(a.x+b.x, a.y+b.y); }
__device__ __forceinline__ float2 csub(float2 a, float2 b){ return make_float2(a.x-b.x, a.y-b.y); }
__device__ __forceinline__ float2 cmul(float2 a, float2 b){
    return make_float2(a.x*b.x - a.y*b.y, a.x*b.y + a.y*b.x);
}
// multiply by DIR*i  (DIR=-1: -i*z ; DIR=+1: +i*z)
template<int DIR>
__device__ __forceinline__ float2 jmul(float2 z){
    return (DIR < 0) ? make_float2(z.y, -z.x) : make_float2(-z.y, z.x);
}

// -------- 8-point DFT (kernel e^{DIR*2*pi*i*r*j/8}) ------------------------
template<int DIR>
__device__ __forceinline__ void dft8(const float2 a[8], float2 B[8]){
    const float C = 0.70710678118654752f;
    // even part: a0,a2,a4,a6
    float2 s0 = cadd(a[0], a[4]), s1 = csub(a[0], a[4]);
    float2 s2 = cadd(a[2], a[6]), s3 = csub(a[2], a[6]);
    float2 e0 = cadd(s0, s2),     e2 = csub(s0, s2);
    float2 js3 = jmul<DIR>(s3);
    float2 e1 = cadd(s1, js3),    e3 = csub(s1, js3);
    // odd part: a1,a3,a5,a7
    float2 u0 = cadd(a[1], a[5]), u1 = csub(a[1], a[5]);
    float2 u2 = cadd(a[3], a[7]), u3 = csub(a[3], a[7]);
    float2 o0 = cadd(u0, u2),     o2 = csub(u0, u2);
    float2 ju3 = jmul<DIR>(u3);
    float2 o1 = cadd(u1, ju3),    o3 = csub(u1, ju3);
    // combine with w8^r
    const float2 w1 = make_float2( C, (DIR < 0) ? -C : C);
    const float2 w3 = make_float2(-C, (DIR < 0) ? -C : C);
    float2 t1 = cmul(w1, o1);
    float2 t2 = jmul<DIR>(o2);
    float2 t3 = cmul(w3, o3);
    B[0] = cadd(e0, o0); B[4] = csub(e0, o0);
    B[1] = cadd(e1, t1); B[5] = csub(e1, t1);
    B[2] = cadd(e2, t2); B[6] = csub(e2, t2);
    B[3] = cadd(e3, t3); B[7] = csub(e3, t3);
}

// -------- one radix-8 Stockham pass (x -> y), s = 1<<LS, s*m = 1024 --------
// FIRST: input is zero for indices >= 4096 (skip those shared reads)
template<int DIR, int LS, bool FIRST>
__device__ __forceinline__ void pass_r8(const float2* __restrict__ x,
                                        float2* __restrict__ y){
    const int s = 1 << LS;
    for (int t = threadIdx.x; t < 1024; t += blockDim.x){
        const int q = t & (s - 1);
        const int p = t >> LS;
        float2 a[8];
        #pragma unroll
        for (int j = 0; j < 8; j++){
            if (FIRST && j >= 4) a[j] = make_float2(0.f, 0.f);
            else                 a[j] = x[t + 1024 * j];
        }
        float2 Bv[8];
        dft8<DIR>(a, Bv);
        // twiddle w1 = e^{DIR*2*pi*i*p/n}, n = 8192>>... (step = 2s in tw base 16384)
        float2 w1 = g_tw[p << (LS + 1)];
        if (DIR > 0) w1.y = -w1.y;
        float2 c[8];
        c[0] = Bv[0];
        float2 w = w1;
        #pragma unroll
        for (int r = 1; r < 8; r++){
            c[r] = cmul(w, Bv[r]);
            if (r < 7) w = cmul(w, w1);
        }
        const int base = q + (p << (LS + 3));
        if (LS == 0){
            // 8 consecutive complex outputs -> 4x 128-bit stores
            float4* y4 = reinterpret_cast<float4*>(y + base);
            #pragma unroll
            for (int i = 0; i < 4; i++)
                y4[i] = make_float4(c[2*i].x, c[2*i].y, c[2*i+1].x, c[2*i+1].y);
        } else {
            #pragma unroll
            for (int r = 0; r < 8; r++)
                y[base + (r << LS)] = c[r];
        }
    }
}

// final radix-2 pass (s = 4096, twiddle = 1, same for both directions)
__device__ __forceinline__ void pass_r2(const float2* __restrict__ x,
                                        float2* __restrict__ y){
    for (int t = threadIdx.x; t < 4096; t += blockDim.x){
        float2 a = x[t], b = x[t + 4096];
        y[t]        = cadd(a, b);
        y[t + 4096] = csub(a, b);
    }
}

// 8192-point complex FFT, input in a, result lands in b (natural order).
template<int DIR, bool FIRST_ZERO>
__device__ __forceinline__ void fft8192(float2* a, float2* b){
    pass_r8<DIR, 0, FIRST_ZERO>(a, b); __syncthreads();
    pass_r8<DIR, 3, false>(b, a);      __syncthreads();
    pass_r8<DIR, 6, false>(a, b);      __syncthreads();
    pass_r8<DIR, 9, false>(b, a);      __syncthreads();
    pass_r2(a, b);                     __syncthreads();
}

// -------- twiddle table ----------------------------------------------------
__global__ void tw_kernel(){
    int k = blockIdx.x * 256 + threadIdx.x;
    if (k < M_){
        double s, c;
        sincospi(-(double)k / 8192.0, &s, &c);   // angle = -pi*k/8192 = -2*pi*k/16384
        g_tw[k] = make_float2((float)c, (float)s);
    }
}

// -------- Hf = rfft(h_g, 16384), bins 0..8192 ------------------------------
__global__ void __launch_bounds__(512) hf_kernel(const float* __restrict__ h){
    extern __shared__ float2 sm[];
    float2* a = sm;
    float2* b = sm + M_;
    const int g = blockIdx.x;
    const float2* h2 = reinterpret_cast<const float2*>(h + (size_t)g * L_);
    for (int i = threadIdx.x; i < 4096; i += blockDim.x) a[i] = h2[i];
    __syncthreads();
    fft8192<-1, true>(a, b);             // Z in b
    float2* Hf = g_Hf + (size_t)g * HFS_;
    for (int k = threadIdx.x; k <= 4096; k += blockDim.x){
        if (k == 0){
            float2 Z0 = b[0];
            Hf[0]    = make_float2(Z0.x + Z0.y, 0.f);
            Hf[8192] = make_float2(Z0.x - Z0.y, 0.f);
        } else if (k == 4096){
            float2 Z = b[4096];
            Hf[4096] = make_float2(Z.x, -Z.y);
        } else {
            float2 Zk = b[k], Zm = b[8192 - k];
            float2 Ze = make_float2(0.5f*(Zk.x + Zm.x), 0.5f*(Zk.y - Zm.y));
            float2 Zo = make_float2(0.5f*(Zk.y + Zm.y), -0.5f*(Zk.x - Zm.x));
            float2 WZo = cmul(g_tw[k], Zo);
            Hf[k] = cadd(Ze, WZo);
            float2 Xm = csub(Ze, WZo);
            Xm.y = -Xm.y;                 // conj
            Hf[8192 - k] = Xm;
        }
    }
}

// -------- pregate + transpose: kv_t(b,d,l) = x2(b,l,d)*v(b,l,d) ------------
__global__ void pregate_transpose(const float* __restrict__ x2,
                                  const float* __restrict__ v){
    __shared__ float tile[32][33];
    const int b  = blockIdx.z;
    const int l0 = blockIdx.x * 32;
    const int d0 = blockIdx.y * 32;
    #pragma unroll
    for (int i = 0; i < 32; i += 8){
        int l = l0 + threadIdx.y + i;
        size_t idx = ((size_t)b * L_ + l) * D_ + d0 + threadIdx.x;
        tile[threadIdx.y + i][threadIdx.x] = x2[idx] * v[idx];
    }
    __syncthreads();
    #pragma unroll
    for (int i = 0; i < 32; i += 8){
        int d = d0 + threadIdx.y + i;
        g_kvt[((size_t)b * D_ + d) * L_ + l0 + threadIdx.x] = tile[threadIdx.x][threadIdx.y + i];
    }
}

// -------- per-channel FFT convolution (in place in g_kvt) ------------------
__global__ void __launch_bounds__(512) conv_kernel(const float* __restrict__ bias){
    extern __shared__ float2 sm[];
    float2* a = sm;
    float2* b = sm + M_;
    const int c = blockIdx.x;                 // c = bidx*D + d
    const int d = c & (D_ - 1);
    const int g = d >> 3;                     // DG_ = 8
    const float2* kv2 = reinterpret_cast<const float2*>(g_kvt + (size_t)c * L_);

    // pack: z[n] = kv[2n] + i*kv[2n+1], n<4096 ; upper half implicit zero
    for (int i = threadIdx.x; i < 4096; i += blockDim.x) a[i] = kv2[i];
    __syncthreads();

    fft8192<-1, true>(a, b);                  // Z in b (natural order)

    // Hermitian unpack * (H + bias) * repack : b -> a
    const float bs = __ldg(bias + d);
    const float2* Hf = g_Hf + (size_t)g * HFS_;
    for (int k = threadIdx.x; k <= 4096; k += blockDim.x){
        if (k == 0){
            float2 Z0 = b[0];
            float X0 = Z0.x + Z0.y;
            float XM = Z0.x - Z0.y;
            float Y0 = X0 * (__ldg(&Hf[0].x)    + bs);
            float YM = XM * (__ldg(&Hf[8192].x) + bs);
            a[0] = make_float2(0.5f*(Y0 + YM), 0.5f*(Y0 - YM));
        } else if (k == 4096){
            float2 Z = b[4096];
            float2 X = make_float2(Z.x, -Z.y);
            float2 Gk = __ldg(&Hf[4096]); Gk.x += bs;
            float2 Y = cmul(X, Gk);
            a[4096] = make_float2(Y.x, -Y.y);
        } else {
            float2 Zk = b[k], Zm = b[8192 - k];
            float2 Ze = make_float2(0.5f*(Zk.x + Zm.x), 0.5f*(Zk.y - Zm.y));
            float2 Zo = make_float2(0.5f*(Zk.y + Zm.y), -0.5f*(Zk.x - Zm.x));
            float2 Wk = g_tw[k];
            float2 WZo = cmul(Wk, Zo);
            float2 Xk = cadd(Ze, WZo);
            float2 Xm = csub(Ze, WZo); Xm.y = -Xm.y;       // conj
            float2 Gk = __ldg(&Hf[k]);        Gk.x += bs;
            float2 Gm = __ldg(&Hf[8192 - k]); Gm.x += bs;
            float2 Yk = cmul(Xk, Gk);
            float2 Ym = cmul(Xm, Gm);
            float2 Ze2 = make_float2(0.5f*(Yk.x + Ym.x), 0.5f*(Yk.y - Ym.y));
            float2 T   = make_float2(0.5f*(Yk.x - Ym.x), 0.5f*(Yk.y + Ym.y));
            float2 Wc  = make_float2(Wk.x, -Wk.y);
            float2 Zo2 = cmul(Wc, T);
            a[k]        = make_float2(Ze2.x - Zo2.y,  Ze2.y + Zo2.x);
            a[8192 - k] = make_float2(Ze2.x + Zo2.y, -Ze2.y + Zo2.x);
        }
    }
    __syncthreads();

    fft8192<+1, false>(a, b);                 // z' in b; y interleaved, scale 1/M

    float2* out2 = reinterpret_cast<float2*>(g_kvt + (size_t)c * L_);
    const float sc = 1.0f / 8192.0f;
    for (int i = threadIdx.x; i < 4096; i += blockDim.x){
        float2 z = b[i];
        out2[i] = make_float2(z.x * sc, z.y * sc);
    }
}

// -------- gate + transpose back: out(b,l,d) = x1(b,l,d) * y_t(b,d,l) -------
__global__ void gate_transpose(const float* __restrict__ x1,
                               float* __restrict__ out){
    __shared__ float tile[32][33];
    const int b  = blockIdx.z;
    const int l0 = blockIdx.x * 32;
    const int d0 = blockIdx.y * 32;
    #pragma unroll
    for (int i = 0; i < 32; i += 8){
        int d = d0 + threadIdx.y + i;
        tile[threadIdx.y + i][threadIdx.x] = g_kvt[((size_t)b * D_ + d) * L_ + l0 + threadIdx.x];
    }
    __syncthreads();
    #pragma unroll
    for (int i = 0; i < 32; i += 8){
        int l = l0 + threadIdx.y + i;
        size_t idx = ((size_t)b * L_ + l) * D_ + d0 + threadIdx.x;
        out[idx] = x1[idx] * tile[threadIdx.x][threadIdx.y + i];
    }
}

// ---------------------------------------------------------------------------
extern "C" void kernel_launch(void* const* d_in, const int* in_sizes, int n_in,
                              void* d_out, int out_size){
    const float* x1   = (const float*)d_in[0];
    const float* x2   = (const float*)d_in[1];
    const float* v    = (const float*)d_in[2];
    const float* h    = (const float*)d_in[3];
    const float* bias = (const float*)d_in[4];
    float* out = (float*)d_out;

    const int SMEM = 2 * M_ * (int)sizeof(float2);   // 131072 B
    cudaFuncSetAttribute(hf_kernel,  cudaFuncAttributeMaxDynamicSharedMemorySize, SMEM);
    cudaFuncSetAttribute(conv_kernel, cudaFuncAttributeMaxDynamicSharedMemorySize, SMEM);

    tw_kernel<<<(M_ + 255) / 256, 256>>>();
    hf_kernel<<<G_, 512, SMEM>>>(h);

    dim3 tgrid(L_ / 32, D_ / 32, B_);
    dim3 tblk(32, 8);
    pregate_transpose<<<tgrid, tblk>>>(x2, v);

    conv_kernel<<<B_ * D_, 512, SMEM>>>(bias);

    gate_transpose<<<tgrid, tblk>>>(x1, out);
}

// round 4
// speedup vs baseline: 1.2390x; 1.2390x over previous
#include <cuda_runtime.h>
#include <math.h>

// Problem constants (fixed instance)
#define B_   2
#define L_   8192
#define G_   256
#define DG_  8
#define D_   2048          // G_*DG_
#define M_   8192          // complex FFT length (= L)
#define HFS_ 8208          // Hf row stride (>= 8193, 16B-multiple)

// -------- device scratch (static: no runtime allocation allowed) ----------
__device__ float  g_kvt[(size_t)B_ * D_ * L_];   // (B, D, L) kv, then y in place
__device__ float2 g_Hf[(size_t)G_ * HFS_];       // rfft(h_g) bins 0..8192
__device__ float2 g_tw[M_];                      // e^{-2*pi*i*k/16384}, k<8192

// smem bank swizzle: injects bits 4..7 into the bank field (bits 0..3).
// Makes both unit-stride and power-of-2-strided float2 access 2-phase (minimal).
__device__ __forceinline__ int sw(int c){ return c ^ ((c >> 4) & 0xF); }

// -------- complex helpers --------------------------------------------------
__device__ __forceinline__ float2 cadd(float2 a, float2 b){ return make_float2(a.x+b.x, a.y+b.y); }
__device__ __forceinline__ float2 csub(float2 a, float2 b){ return make_float2(a.x-b.x, a.y-b.y); }
__device__ __forceinline__ float2 cmul(float2 a, float2 b){
    return make_float2(a.x*b.x - a.y*b.y, a.x*b.y + a.y*b.x);
}
// multiply by DIR*i  (DIR=-1: -i*z ; DIR=+1: +i*z)
template<int DIR>
__device__ __forceinline__ float2 jmul(float2 z){
    return (DIR < 0) ? make_float2(z.y, -z.x) : make_float2(-z.y, z.x);
}

// -------- 8-point DFT (kernel e^{DIR*2*pi*i*r*j/8}) ------------------------
template<int DIR>
__device__ __forceinline__ void dft8(const float2 a[8], float2 B[8]){
    const float C = 0.70710678118654752f;
    float2 s0 = cadd(a[0], a[4]), s1 = csub(a[0], a[4]);
    float2 s2 = cadd(a[2], a[6]), s3 = csub(a[2], a[6]);
    float2 e0 = cadd(s0, s2),     e2 = csub(s0, s2);
    float2 js3 = jmul<DIR>(s3);
    float2 e1 = cadd(s1, js3),    e3 = csub(s1, js3);
    float2 u0 = cadd(a[1], a[5]), u1 = csub(a[1], a[5]);
    float2 u2 = cadd(a[3], a[7]), u3 = csub(a[3], a[7]);
    float2 o0 = cadd(u0, u2),     o2 = csub(u0, u2);
    float2 ju3 = jmul<DIR>(u3);
    float2 o1 = cadd(u1, ju3),    o3 = csub(u1, ju3);
    const float2 w1 = make_float2( C, (DIR < 0) ? -C : C);
    const float2 w3 = make_float2(-C, (DIR < 0) ? -C : C);
    float2 t1 = cmul(w1, o1);
    float2 t2 = jmul<DIR>(o2);
    float2 t3 = cmul(w3, o3);
    B[0] = cadd(e0, o0); B[4] = csub(e0, o0);
    B[1] = cadd(e1, t1); B[5] = csub(e1, t1);
    B[2] = cadd(e2, t2); B[6] = csub(e2, t2);
    B[3] = cadd(e3, t3); B[7] = csub(e3, t3);
}

// -------- one radix-8 Stockham pass (x -> y), s = 1<<LS ---------------------
// FIRST: input is zero for indices >= 4096 (skip those shared reads)
template<int DIR, int LS, bool FIRST>
__device__ __forceinline__ void pass_r8(const float2* __restrict__ x,
                                        float2* __restrict__ y){
    const int s = 1 << LS;
    for (int t = threadIdx.x; t < 1024; t += blockDim.x){
        const int q = t & (s - 1);
        const int p = t >> LS;
        float2 a[8];
        #pragma unroll
        for (int j = 0; j < 8; j++){
            if (FIRST && j >= 4) a[j] = make_float2(0.f, 0.f);
            else                 a[j] = x[sw(t + 1024 * j)];
        }
        float2 Bv[8];
        dft8<DIR>(a, Bv);
        float2 w1 = g_tw[p << (LS + 1)];
        if (DIR > 0) w1.y = -w1.y;
        float2 c[8];
        c[0] = Bv[0];
        float2 w = w1;
        #pragma unroll
        for (int r = 1; r < 8; r++){
            c[r] = cmul(w, Bv[r]);
            if (r < 7) w = cmul(w, w1);
        }
        const int base = q + (p << (LS + 3));
        #pragma unroll
        for (int r = 0; r < 8; r++)
            y[sw(base + (r << LS))] = c[r];
    }
}

// -------- final radix-16 pass: s = 512, p = 0 -> unit twiddles --------------
template<int DIR>
__device__ __forceinline__ void pass_r16(const float2* __restrict__ x,
                                         float2* __restrict__ y){
    const float C  = 0.70710678118654752f;
    const float c1 = 0.92387953251128676f;
    const float s1 = 0.38268343236508977f;
    const float wr[8] = {1.f,  c1,  C,  s1, 0.f, -s1, -C, -c1};
    const float wis[8] = {0.f, -s1, -C, -c1, -1.f, -c1, -C, -s1};
    for (int t = threadIdx.x; t < 512; t += blockDim.x){
        float2 ein[8];
        #pragma unroll
        for (int j = 0; j < 8; j++) ein[j] = x[sw(t + 1024 * j)];        // even p = 2j
        float2 E[8];
        dft8<DIR>(ein, E);
        float2 oin[8];
        #pragma unroll
        for (int j = 0; j < 8; j++) oin[j] = x[sw(t + 512 + 1024 * j)];  // odd p = 2j+1
        float2 O[8];
        dft8<DIR>(oin, O);
        #pragma unroll
        for (int k = 0; k < 8; k++){
            float wi = (DIR < 0) ? wis[k] : -wis[k];
            float2 tt = make_float2(wr[k]*O[k].x - wi*O[k].y,
                                    wr[k]*O[k].y + wi*O[k].x);
            y[sw(t + (k << 9))]         = cadd(E[k], tt);
            y[sw(t + ((k + 8) << 9))]   = csub(E[k], tt);
        }
    }
}

// 8192-point complex FFT (8*8*8*16). Input in a, RESULT lands back in a.
template<int DIR, bool FIRST_ZERO>
__device__ __forceinline__ void fft8192(float2* a, float2* b){
    pass_r8<DIR, 0, FIRST_ZERO>(a, b); __syncthreads();
    pass_r8<DIR, 3, false>(b, a);      __syncthreads();
    pass_r8<DIR, 6, false>(a, b);      __syncthreads();
    pass_r16<DIR>(b, a);               __syncthreads();
}

// -------- twiddle table ----------------------------------------------------
__global__ void tw_kernel(){
    int k = blockIdx.x * 256 + threadIdx.x;
    if (k < M_){
        double s, c;
        sincospi(-(double)k / 8192.0, &s, &c);   // angle = -2*pi*k/16384
        g_tw[k] = make_float2((float)c, (float)s);
    }
}

// -------- Hf = rfft(h_g, 16384), bins 0..8192 ------------------------------
__global__ void __launch_bounds__(1024) hf_kernel(const float* __restrict__ h){
    extern __shared__ float2 sm[];
    float2* a = sm;
    float2* b = sm + M_;
    const int g = blockIdx.x;
    const float2* h2 = reinterpret_cast<const float2*>(h + (size_t)g * L_);
    for (int i = threadIdx.x; i < 4096; i += blockDim.x) a[sw(i)] = h2[i];
    __syncthreads();
    fft8192<-1, true>(a, b);             // Z in a
    float2* Hf = g_Hf + (size_t)g * HFS_;
    for (int k = threadIdx.x; k <= 4096; k += blockDim.x){
        if (k == 0){
            float2 Z0 = a[sw(0)];
            Hf[0]    = make_float2(Z0.x + Z0.y, 0.f);
            Hf[8192] = make_float2(Z0.x - Z0.y, 0.f);
        } else if (k == 4096){
            float2 Z = a[sw(4096)];
            Hf[4096] = make_float2(Z.x, -Z.y);
        } else {
            float2 Zk = a[sw(k)], Zm = a[sw(8192 - k)];
            float2 Ze = make_float2(0.5f*(Zk.x + Zm.x), 0.5f*(Zk.y - Zm.y));
            float2 Zo = make_float2(0.5f*(Zk.y + Zm.y), -0.5f*(Zk.x - Zm.x));
            float2 WZo = cmul(g_tw[k], Zo);
            Hf[k] = cadd(Ze, WZo);
            float2 Xm = csub(Ze, WZo);
            Xm.y = -Xm.y;                 // conj
            Hf[8192 - k] = Xm;
        }
    }
}

// -------- pregate + transpose: kv_t(b,d,l) = x2(b,l,d)*v(b,l,d) ------------
__global__ void pregate_transpose(const float* __restrict__ x2,
                                  const float* __restrict__ v){
    __shared__ float tile[32][33];
    const int b  = blockIdx.z;
    const int l0 = blockIdx.x * 32;
    const int d0 = blockIdx.y * 32;
    #pragma unroll
    for (int i = 0; i < 32; i += 8){
        int l = l0 + threadIdx.y + i;
        size_t idx = ((size_t)b * L_ + l) * D_ + d0 + threadIdx.x;
        tile[threadIdx.y + i][threadIdx.x] = x2[idx] * v[idx];
    }
    __syncthreads();
    #pragma unroll
    for (int i = 0; i < 32; i += 8){
        int d = d0 + threadIdx.y + i;
        g_kvt[((size_t)b * D_ + d) * L_ + l0 + threadIdx.x] = tile[threadIdx.x][threadIdx.y + i];
    }
}

// -------- per-channel FFT convolution (in place in g_kvt) ------------------
__global__ void __launch_bounds__(1024) conv_kernel(const float* __restrict__ bias){
    extern __shared__ float2 sm[];
    float2* a = sm;
    float2* b = sm + M_;
    const int c = blockIdx.x;                 // c = bidx*D + d
    const int d = c & (D_ - 1);
    const int g = d >> 3;                     // DG_ = 8
    const float2* kv2 = reinterpret_cast<const float2*>(g_kvt + (size_t)c * L_);

    // pack: z[n] = kv[2n] + i*kv[2n+1], n<4096 ; upper half implicit zero
    for (int i = threadIdx.x; i < 4096; i += blockDim.x) a[sw(i)] = kv2[i];
    __syncthreads();

    fft8192<-1, true>(a, b);                  // Z in a (natural order)

    // Hermitian unpack * (H + bias) * repack — fully IN PLACE in a:
    // thread handling k touches exactly {k, 8192-k}, read-then-write, no race.
    const float bs = __ldg(bias + d);
    const float2* Hf = g_Hf + (size_t)g * HFS_;
    for (int k = threadIdx.x; k <= 4096; k += blockDim.x){
        if (k == 0){
            float2 Z0 = a[sw(0)];
            float X0 = Z0.x + Z0.y;
            float XM = Z0.x - Z0.y;
            float Y0 = X0 * (__ldg(&Hf[0].x)    + bs);
            float YM = XM * (__ldg(&Hf[8192].x) + bs);
            a[sw(0)] = make_float2(0.5f*(Y0 + YM), 0.5f*(Y0 - YM));
        } else if (k == 4096){
            float2 Z = a[sw(4096)];
            float2 X = make_float2(Z.x, -Z.y);
            float2 Gk = __ldg(&Hf[4096]); Gk.x += bs;
            float2 Y = cmul(X, Gk);
            a[sw(4096)] = make_float2(Y.x, -Y.y);
        } else {
            float2 Zk = a[sw(k)], Zm = a[sw(8192 - k)];
            float2 Ze = make_float2(0.5f*(Zk.x + Zm.x), 0.5f*(Zk.y - Zm.y));
            float2 Zo = make_float2(0.5f*(Zk.y + Zm.y), -0.5f*(Zk.x - Zm.x));
            float2 Wk = g_tw[k];
            float2 WZo = cmul(Wk, Zo);
            float2 Xk = cadd(Ze, WZo);
            float2 Xm = csub(Ze, WZo); Xm.y = -Xm.y;       // conj
            float2 Gk = __ldg(&Hf[k]);        Gk.x += bs;
            float2 Gm = __ldg(&Hf[8192 - k]); Gm.x += bs;
            float2 Yk = cmul(Xk, Gk);
            float2 Ym = cmul(Xm, Gm);
            float2 Ze2 = make_float2(0.5f*(Yk.x + Ym.x), 0.5f*(Yk.y - Ym.y));
            float2 T   = make_float2(0.5f*(Yk.x - Ym.x), 0.5f*(Yk.y + Ym.y));
            float2 Wc  = make_float2(Wk.x, -Wk.y);
            float2 Zo2 = cmul(Wc, T);
            a[sw(k)]        = make_float2(Ze2.x - Zo2.y,  Ze2.y + Zo2.x);
            a[sw(8192 - k)] = make_float2(Ze2.x + Zo2.y, -Ze2.y + Zo2.x);
        }
    }
    __syncthreads();

    fft8192<+1, false>(a, b);                 // result in a; y interleaved, scale 1/M

    float2* out2 = reinterpret_cast<float2*>(g_kvt + (size_t)c * L_);
    const float sc = 1.0f / 8192.0f;
    for (int i = threadIdx.x; i < 4096; i += blockDim.x){
        float2 z = a[sw(i)];
        out2[i] = make_float2(z.x * sc, z.y * sc);
    }
}

// -------- gate + transpose back: out(b,l,d) = x1(b,l,d) * y_t(b,d,l) -------
__global__ void gate_transpose(const float* __restrict__ x1,
                               float* __restrict__ out){
    __shared__ float tile[32][33];
    const int b  = blockIdx.z;
    const int l0 = blockIdx.x * 32;
    const int d0 = blockIdx.y * 32;
    #pragma unroll
    for (int i = 0; i < 32; i += 8){
        int d = d0 + threadIdx.y + i;
        tile[threadIdx.y + i][threadIdx.x] = g_kvt[((size_t)b * D_ + d) * L_ + l0 + threadIdx.x];
    }
    __syncthreads();
    #pragma unroll
    for (int i = 0; i < 32; i += 8){
        int l = l0 + threadIdx.y + i;
        size_t idx = ((size_t)b * L_ + l) * D_ + d0 + threadIdx.x;
        out[idx] = x1[idx] * tile[threadIdx.x][threadIdx.y + i];
    }
}

// ---------------------------------------------------------------------------
extern "C" void kernel_launch(void* const* d_in, const int* in_sizes, int n_in,
                              void* d_out, int out_size){
    const float* x1   = (const float*)d_in[0];
    const float* x2   = (const float*)d_in[1];
    const float* v    = (const float*)d_in[2];
    const float* h    = (const float*)d_in[3];
    const float* bias = (const float*)d_in[4];
    float* out = (float*)d_out;

    const int SMEM = 2 * M_ * (int)sizeof(float2);   // 131072 B
    cudaFuncSetAttribute(hf_kernel,   cudaFuncAttributeMaxDynamicSharedMemorySize, SMEM);
    cudaFuncSetAttribute(conv_kernel, cudaFuncAttributeMaxDynamicSharedMemorySize, SMEM);

    tw_kernel<<<(M_ + 255) / 256, 256>>>();
    hf_kernel<<<G_, 1024, SMEM>>>(h);

    dim3 tgrid(L_ / 32, D_ / 32, B_);
    dim3 tblk(32, 8);
    pregate_transpose<<<tgrid, tblk>>>(x2, v);

    conv_kernel<<<B_ * D_, 1024, SMEM>>>(bias);

    gate_transpose<<<tgrid, tblk>>>(x1, out);
}